// round 1
// baseline (speedup 1.0000x reference)
#include <cuda_runtime.h>
#include <cuda_bf16.h>

// MoE gather-combine: out[t, :] = sum_k scores[t*K+k] * flat[slots[t*K+k], :]
// Pure HBM-streaming problem. One CTA per token, float4 vector loads/stores.

// Fast path: hidden == 2048, 256 threads, each thread owns 2 float4 (=8 floats).
__global__ void __launch_bounds__(256, 8)
moe_gather_h2048_kernel(const float* __restrict__ flat,
                        const float* __restrict__ scores,
                        const int* __restrict__ slots,
                        const int* __restrict__ topk_p,
                        float* __restrict__ out,
                        int n_tokens) {
    const int token = blockIdx.x;
    if (token >= n_tokens) return;
    const int K = topk_p[0];

    const int t0 = threadIdx.x;          // float4 index 0..255
    const int t1 = threadIdx.x + 256;    // float4 index 256..511

    float4 acc0 = make_float4(0.f, 0.f, 0.f, 0.f);
    float4 acc1 = make_float4(0.f, 0.f, 0.f, 0.f);

    #pragma unroll 2
    for (int k = 0; k < K; ++k) {
        const int   slot = __ldg(&slots[token * K + k]);
        const float w    = __ldg(&scores[token * K + k]);
        const float4* row = reinterpret_cast<const float4*>(flat + (size_t)slot * 2048);
        float4 v0 = __ldg(&row[t0]);
        float4 v1 = __ldg(&row[t1]);
        acc0.x = fmaf(w, v0.x, acc0.x);
        acc0.y = fmaf(w, v0.y, acc0.y);
        acc0.z = fmaf(w, v0.z, acc0.z);
        acc0.w = fmaf(w, v0.w, acc0.w);
        acc1.x = fmaf(w, v1.x, acc1.x);
        acc1.y = fmaf(w, v1.y, acc1.y);
        acc1.z = fmaf(w, v1.z, acc1.z);
        acc1.w = fmaf(w, v1.w, acc1.w);
    }

    float4* orow = reinterpret_cast<float4*>(out + (size_t)token * 2048);
    orow[t0] = acc0;
    orow[t1] = acc1;
}

// Generic fallback for any hidden / top_k (scalar loop, grid-stride within row).
__global__ void moe_gather_generic_kernel(const float* __restrict__ flat,
                                          const float* __restrict__ scores,
                                          const int* __restrict__ slots,
                                          const int* __restrict__ topk_p,
                                          float* __restrict__ out,
                                          int n_tokens, int hidden) {
    const int token = blockIdx.x;
    if (token >= n_tokens) return;
    const int K = topk_p[0];

    for (int h = threadIdx.x; h < hidden; h += blockDim.x) {
        float acc = 0.f;
        for (int k = 0; k < K; ++k) {
            const int   slot = slots[token * K + k];
            const float w    = scores[token * K + k];
            acc = fmaf(w, flat[(size_t)slot * hidden + h], acc);
        }
        out[(size_t)token * hidden + h] = acc;
    }
}

extern "C" void kernel_launch(void* const* d_in, const int* in_sizes, int n_in,
                              void* d_out, int out_size) {
    const float* flat   = (const float*)d_in[0];   // moe_output, [n_slots, hidden] flattened
    const float* scores = (const float*)d_in[1];   // [n_slots]
    const int*   slots  = (const int*)d_in[2];     // [n_slots]
    const int*   topk_p = (const int*)d_in[3];     // scalar top_k on device

    const int n_slots = in_sizes[1];
    const int hidden  = in_sizes[0] / n_slots;
    // n_tokens = n_slots / top_k; out_size = n_tokens * hidden, so:
    const int n_tokens = out_size / hidden;

    float* out = (float*)d_out;

    if (hidden == 2048) {
        moe_gather_h2048_kernel<<<n_tokens, 256>>>(flat, scores, slots, topk_p,
                                                   out, n_tokens);
    } else {
        moe_gather_generic_kernel<<<n_tokens, 256>>>(flat, scores, slots, topk_p,
                                                     out, n_tokens, hidden);
    }
}

// round 2
// speedup vs baseline: 1.0654x; 1.0654x over previous
#include <cuda_runtime.h>
#include <cuda_bf16.h>

// MoE gather-combine: out[t, :] = sum_k scores[t*K+k] * flat[slots[t*K+k], :]
// HBM-bound. flat (128MB) ~fits in L2 (126MB) -> protect L2 residency:
//   - streaming (evict-first) stores for the never-re-read output
//   - K==2 specialized path: all 4 row LDG.128 issued back-to-back (MLP=4)

__device__ __forceinline__ void stcs_f4(float4* p, float4 v) {
    asm volatile("st.global.cs.v4.f32 [%0], {%1,%2,%3,%4};"
                 :: "l"(p), "f"(v.x), "f"(v.y), "f"(v.z), "f"(v.w) : "memory");
}

__global__ void __launch_bounds__(256, 8)
moe_gather_h2048_kernel(const float* __restrict__ flat,
                        const float* __restrict__ scores,
                        const int* __restrict__ slots,
                        const int* __restrict__ topk_p,
                        float* __restrict__ out,
                        int n_tokens) {
    const int token = blockIdx.x;
    if (token >= n_tokens) return;
    const int K = topk_p[0];

    const int t0 = threadIdx.x;          // float4 index 0..255
    const int t1 = threadIdx.x + 256;    // float4 index 256..511
    float4* orow = reinterpret_cast<float4*>(out + (size_t)token * 2048);

    if (K == 2) {
        // Front-load both slot/weight reads, then 4 independent LDG.128.
        const int   s0 = __ldg(&slots[token * 2 + 0]);
        const int   s1 = __ldg(&slots[token * 2 + 1]);
        const float w0 = __ldg(&scores[token * 2 + 0]);
        const float w1 = __ldg(&scores[token * 2 + 1]);

        const float4* r0 = reinterpret_cast<const float4*>(flat + (size_t)s0 * 2048);
        const float4* r1 = reinterpret_cast<const float4*>(flat + (size_t)s1 * 2048);

        float4 a0 = __ldg(&r0[t0]);
        float4 a1 = __ldg(&r0[t1]);
        float4 b0 = __ldg(&r1[t0]);
        float4 b1 = __ldg(&r1[t1]);

        float4 acc0, acc1;
        acc0.x = fmaf(w1, b0.x, w0 * a0.x);
        acc0.y = fmaf(w1, b0.y, w0 * a0.y);
        acc0.z = fmaf(w1, b0.z, w0 * a0.z);
        acc0.w = fmaf(w1, b0.w, w0 * a0.w);
        acc1.x = fmaf(w1, b1.x, w0 * a1.x);
        acc1.y = fmaf(w1, b1.y, w0 * a1.y);
        acc1.z = fmaf(w1, b1.z, w0 * a1.z);
        acc1.w = fmaf(w1, b1.w, w0 * a1.w);

        stcs_f4(&orow[t0], acc0);
        stcs_f4(&orow[t1], acc1);
        return;
    }

    // Generic K path
    float4 acc0 = make_float4(0.f, 0.f, 0.f, 0.f);
    float4 acc1 = make_float4(0.f, 0.f, 0.f, 0.f);
    for (int k = 0; k < K; ++k) {
        const int   slot = __ldg(&slots[token * K + k]);
        const float w    = __ldg(&scores[token * K + k]);
        const float4* row = reinterpret_cast<const float4*>(flat + (size_t)slot * 2048);
        float4 v0 = __ldg(&row[t0]);
        float4 v1 = __ldg(&row[t1]);
        acc0.x = fmaf(w, v0.x, acc0.x);
        acc0.y = fmaf(w, v0.y, acc0.y);
        acc0.z = fmaf(w, v0.z, acc0.z);
        acc0.w = fmaf(w, v0.w, acc0.w);
        acc1.x = fmaf(w, v1.x, acc1.x);
        acc1.y = fmaf(w, v1.y, acc1.y);
        acc1.z = fmaf(w, v1.z, acc1.z);
        acc1.w = fmaf(w, v1.w, acc1.w);
    }
    stcs_f4(&orow[t0], acc0);
    stcs_f4(&orow[t1], acc1);
}

// Generic fallback for any hidden (scalar loop within row).
__global__ void moe_gather_generic_kernel(const float* __restrict__ flat,
                                          const float* __restrict__ scores,
                                          const int* __restrict__ slots,
                                          const int* __restrict__ topk_p,
                                          float* __restrict__ out,
                                          int n_tokens, int hidden) {
    const int token = blockIdx.x;
    if (token >= n_tokens) return;
    const int K = topk_p[0];

    for (int h = threadIdx.x; h < hidden; h += blockDim.x) {
        float acc = 0.f;
        for (int k = 0; k < K; ++k) {
            const int   slot = slots[token * K + k];
            const float w    = scores[token * K + k];
            acc = fmaf(w, flat[(size_t)slot * hidden + h], acc);
        }
        out[(size_t)token * hidden + h] = acc;
    }
}

extern "C" void kernel_launch(void* const* d_in, const int* in_sizes, int n_in,
                              void* d_out, int out_size) {
    const float* flat   = (const float*)d_in[0];   // moe_output, [n_slots, hidden] flattened
    const float* scores = (const float*)d_in[1];   // [n_slots]
    const int*   slots  = (const int*)d_in[2];     // [n_slots]
    const int*   topk_p = (const int*)d_in[3];     // scalar top_k on device

    const int n_slots = in_sizes[1];
    const int hidden  = in_sizes[0] / n_slots;
    const int n_tokens = out_size / hidden;

    float* out = (float*)d_out;

    if (hidden == 2048) {
        moe_gather_h2048_kernel<<<n_tokens, 256>>>(flat, scores, slots, topk_p,
                                                   out, n_tokens);
    } else {
        moe_gather_generic_kernel<<<n_tokens, 256>>>(flat, scores, slots, topk_p,
                                                     out, n_tokens, hidden);
    }
}